// round 3
// baseline (speedup 1.0000x reference)
#include <cuda_runtime.h>
#include <math.h>

#define BATCH 16
#define DIM   48
#define HID   16
#define CH    8
#define IMG   256
#define HW    (IMG*IMG)

#define TX 32
#define TY 16
#define HAW (TX+2)      // 34
#define HAH (TY+2)      // 18
#define NH  (HAW*HAH)   // 612
#define NT  256
#define NOUT (TX*TY)    // 512

typedef unsigned long long u64;

__device__ __forceinline__ u64 pk2(float a, float b) {
    u64 r;
    asm("mov.b64 %0,{%1,%2};" : "=l"(r) : "r"(__float_as_uint(a)), "r"(__float_as_uint(b)));
    return r;
}
__device__ __forceinline__ void upk2(u64 v, float& a, float& b) {
    unsigned lo, hi;
    asm("mov.b64 {%0,%1},%2;" : "=r"(lo), "=r"(hi) : "l"(v));
    a = __uint_as_float(lo); b = __uint_as_float(hi);
}
__device__ __forceinline__ void fma2(u64& d, u64 a, u64 b) {
    asm("fma.rn.f32x2 %0,%1,%2,%0;" : "+l"(d) : "l"(a), "l"(b));
}
__device__ __forceinline__ u64 mul2(u64 a, u64 b) {
    u64 r;
    asm("mul.rn.f32x2 %0,%1,%2;" : "=l"(r) : "l"(a), "l"(b));
    return r;
}

// Exact-formula GELU via Abramowitz&Stegun 7.1.26 erf (|abs err| ~1.5e-7)
__device__ __forceinline__ float gelu_f(float v) {
    float s = fabsf(v) * 0.7071067811865476f;
    float t = __fdividef(1.0f, fmaf(0.3275911f, s, 1.0f));
    float p = fmaf(1.061405429f, t, -1.453152027f);
    p = fmaf(p, t, 1.421413741f);
    p = fmaf(p, t, -0.284496736f);
    p = fmaf(p, t, 0.254829592f);
    p *= t;
    float e = fmaf(-p, __expf(-s * s), 1.0f);   // erf(s), s>=0
    e = copysignf(e, v);
    return 0.5f * v * (1.0f + e);
}

__global__ __launch_bounds__(NT) void fused_dclf(
    const float* __restrict__ x,    const float* __restrict__ W1,
    const float* __restrict__ b1,   const float* __restrict__ gamma,
    const float* __restrict__ beta, const float* __restrict__ dw_w,
    const float* __restrict__ dw_b, const float* __restrict__ pw_w,
    const float* __restrict__ pw_b, const float* __restrict__ W2,
    const float* __restrict__ b2,   float* __restrict__ out)
{
    __shared__ __align__(16) float sW1[DIM * HID];   // 3 KB
    __shared__ u64  sb1_2[HID / 2];
    __shared__ float sg[CH], sb[CH];
    __shared__ float4 snA[NH], snB[NH];              // 19.1 KB
    __shared__ float4 sx1A[NOUT], sx1B[NOUT];        // 16 KB
    __shared__ u64  sdw2[9 * 4];
    __shared__ u64  sdwb2[4];
    __shared__ u64  spw2[CH * 4];
    __shared__ u64  spwb2[4];
    __shared__ __align__(16) float sW2[CH * DIM];    // 1.5 KB
    __shared__ u64  sb2_2[DIM / 2];

    const int tid = threadIdx.x;

    // ---- stage weights / prepack channel-pairs ----
    for (int i = tid; i < DIM * HID; i += NT) sW1[i] = W1[i];
    for (int i = tid; i < CH * DIM;  i += NT) sW2[i] = W2[i];
    if (tid < HID / 2) sb1_2[tid] = pk2(b1[2 * tid], b1[2 * tid + 1]);
    if (tid < CH) { sg[tid] = gamma[tid]; sb[tid] = beta[tid]; }
    if (tid < 36) {                                  // dw: [tap][chpair]
        int tap = tid / 4, q = tid % 4;
        sdw2[tid] = pk2(dw_w[(2 * q) * 9 + tap], dw_w[(2 * q + 1) * 9 + tap]);
    }
    if (tid >= 64 && tid < 68) {
        int q = tid - 64;
        sdwb2[q] = pk2(dw_b[2 * q], dw_b[2 * q + 1]);
    }
    if (tid >= 96 && tid < 128) {                    // pw: [cin][coutpair]
        int c = (tid - 96) / 4, j = (tid - 96) % 4;
        spw2[tid - 96] = pk2(pw_w[(2 * j) * CH + c], pw_w[(2 * j + 1) * CH + c]);
    }
    if (tid >= 128 && tid < 132) {
        int q = tid - 128;
        spwb2[q] = pk2(pw_b[2 * q], pw_b[2 * q + 1]);
    }
    if (tid >= 160 && tid < 184) {
        int q = tid - 160;
        sb2_2[q] = pk2(b2[2 * q], b2[2 * q + 1]);
    }
    __syncthreads();

    const int b   = blockIdx.z;
    const int tx0 = blockIdx.x * TX;
    const int ty0 = blockIdx.y * TY;
    const float* xb = x + (size_t)b * HW * DIM;

    // =========================================================
    // Phase 1: GEMM1 + gelu^2 + LN over the halo tile -> smem
    // =========================================================
    for (int i = tid; i < NH; i += NT) {
        int hy = i / HAW, hx = i % HAW;
        int gy = ty0 + hy - 1, gx = tx0 + hx - 1;
        bool inimg = ((unsigned)gy < IMG) & ((unsigned)gx < IMG);
        if (!inimg) {   // SAME zero-padding of the conv input
            snA[i] = make_float4(0.f, 0.f, 0.f, 0.f);
            snB[i] = make_float4(0.f, 0.f, 0.f, 0.f);
            continue;
        }
        const float4* xr = (const float4*)(xb + ((size_t)gy * IMG + gx) * DIM);

        u64 z2[8];
        #pragma unroll
        for (int q = 0; q < 8; q++) z2[q] = sb1_2[q];

        #pragma unroll
        for (int k4 = 0; k4 < DIM / 4; k4++) {
            float4 v = xr[k4];
            float xs[4] = {v.x, v.y, v.z, v.w};
            #pragma unroll
            for (int kk = 0; kk < 4; kk++) {
                u64 xx = pk2(xs[kk], xs[kk]);
                const ulonglong2* wr = (const ulonglong2*)&sW1[(k4 * 4 + kk) * HID];
                #pragma unroll
                for (int q2 = 0; q2 < 4; q2++) {
                    ulonglong2 w = wr[q2];
                    fma2(z2[2 * q2],     xx, w.x);
                    fma2(z2[2 * q2 + 1], xx, w.y);
                }
            }
        }

        float z[HID];
        #pragma unroll
        for (int q = 0; q < 8; q++) upk2(z2[q], z[2 * q], z[2 * q + 1]);

        // x1 half only needed for interior (output) pixels
        bool interior = (hy >= 1) & (hy <= TY) & (hx >= 1) & (hx <= TX);
        if (interior) {
            float t0[CH];
            #pragma unroll
            for (int j = 0; j < CH; j++) t0[j] = gelu_f(gelu_f(z[j]));
            int oi = (hy - 1) * TX + (hx - 1);
            sx1A[oi] = make_float4(t0[0], t0[1], t0[2], t0[3]);
            sx1B[oi] = make_float4(t0[4], t0[5], t0[6], t0[7]);
        }

        // LN half
        float t1[CH];
        #pragma unroll
        for (int j = 0; j < CH; j++) t1[j] = gelu_f(gelu_f(z[8 + j]));
        float m = 0.f;
        #pragma unroll
        for (int j = 0; j < CH; j++) m += t1[j];
        m *= 0.125f;
        float var = 0.f;
        #pragma unroll
        for (int j = 0; j < CH; j++) { float d = t1[j] - m; var += d * d; }
        var *= 0.125f;
        float inv = rsqrtf(var + 1e-5f);
        float nn[CH];
        #pragma unroll
        for (int j = 0; j < CH; j++) nn[j] = (t1[j] - m) * inv * sg[j] + sb[j];
        snA[i] = make_float4(nn[0], nn[1], nn[2], nn[3]);
        snB[i] = make_float4(nn[4], nn[5], nn[6], nn[7]);
    }
    __syncthreads();

    // =========================================================
    // Phase 2: dw3x3 + pw1x1 + gate + GEMM(8->48) + store
    // =========================================================
    const ulonglong2* snA2  = (const ulonglong2*)snA;
    const ulonglong2* snB2  = (const ulonglong2*)snB;
    const ulonglong2* sx1A2 = (const ulonglong2*)sx1A;
    const ulonglong2* sx1B2 = (const ulonglong2*)sx1B;
    const ulonglong2* sW2_2 = (const ulonglong2*)sW2;

    #pragma unroll
    for (int rep = 0; rep < NOUT / NT; rep++) {
        int o  = tid + rep * NT;
        int oy = o / TX, ox = o % TX;
        int ci = (oy + 1) * HAW + (ox + 1);

        // depthwise 3x3 on channel pairs
        u64 sp2[4];
        #pragma unroll
        for (int q = 0; q < 4; q++) sp2[q] = sdwb2[q];
        u64 cenA0 = 0, cenA1 = 0, cenB0 = 0, cenB1 = 0;
        #pragma unroll
        for (int dy = 0; dy < 3; dy++) {
            #pragma unroll
            for (int dx = 0; dx < 3; dx++) {
                int idx = ci + (dy - 1) * HAW + (dx - 1);
                ulonglong2 a  = snA2[idx];
                ulonglong2 bv = snB2[idx];
                int tap = dy * 3 + dx;
                fma2(sp2[0], a.x,  sdw2[tap * 4 + 0]);
                fma2(sp2[1], a.y,  sdw2[tap * 4 + 1]);
                fma2(sp2[2], bv.x, sdw2[tap * 4 + 2]);
                fma2(sp2[3], bv.y, sdw2[tap * 4 + 3]);
                if (tap == 4) { cenA0 = a.x; cenA1 = a.y; cenB0 = bv.x; cenB1 = bv.y; }
            }
        }

        // pointwise 1x1 (8 -> 8)
        float nc[CH];
        upk2(cenA0, nc[0], nc[1]); upk2(cenA1, nc[2], nc[3]);
        upk2(cenB0, nc[4], nc[5]); upk2(cenB1, nc[6], nc[7]);
        u64 ch2[4];
        #pragma unroll
        for (int q = 0; q < 4; q++) ch2[q] = spwb2[q];
        #pragma unroll
        for (int c = 0; c < CH; c++) {
            u64 cc = pk2(nc[c], nc[c]);
            #pragma unroll
            for (int q = 0; q < 4; q++) fma2(ch2[q], cc, spw2[c * 4 + q]);
        }

        // gate: g = x1 * sp * ch
        ulonglong2 xa = sx1A2[o], xv = sx1B2[o];
        u64 g2[4];
        g2[0] = mul2(mul2(xa.x, sp2[0]), ch2[0]);
        g2[1] = mul2(mul2(xa.y, sp2[1]), ch2[1]);
        g2[2] = mul2(mul2(xv.x, sp2[2]), ch2[2]);
        g2[3] = mul2(mul2(xv.y, sp2[3]), ch2[3]);
        float g[CH];
        #pragma unroll
        for (int q = 0; q < 4; q++) upk2(g2[q], g[2 * q], g[2 * q + 1]);

        // GEMM 8 -> 48
        u64 acc[DIM / 2];
        #pragma unroll
        for (int q = 0; q < DIM / 2; q++) acc[q] = sb2_2[q];
        #pragma unroll
        for (int c = 0; c < CH; c++) {
            u64 gg = pk2(g[c], g[c]);
            const ulonglong2* wr = sW2_2 + c * (DIM / 4);
            #pragma unroll
            for (int q = 0; q < DIM / 4; q++) {
                ulonglong2 w = wr[q];
                fma2(acc[2 * q],     gg, w.x);
                fma2(acc[2 * q + 1], gg, w.y);
            }
        }

        // transposed (d-major) coalesced store
        int p = (ty0 + oy) * IMG + (tx0 + ox);
        float* ob = out + (size_t)b * DIM * HW + p;
        #pragma unroll
        for (int q = 0; q < DIM / 2; q++) {
            float f0, f1;
            upk2(acc[q], f0, f1);
            ob[(size_t)(2 * q)     * HW] = f0;
            ob[(size_t)(2 * q + 1) * HW] = f1;
        }
    }
}

extern "C" void kernel_launch(void* const* d_in, const int* in_sizes, int n_in,
                              void* d_out, int out_size)
{
    const float* x     = (const float*)d_in[0];
    const float* W1    = (const float*)d_in[1];
    const float* b1    = (const float*)d_in[2];
    const float* gamma = (const float*)d_in[3];
    const float* beta  = (const float*)d_in[4];
    const float* dw_w  = (const float*)d_in[5];
    const float* dw_b  = (const float*)d_in[6];
    const float* pw_w  = (const float*)d_in[7];
    const float* pw_b  = (const float*)d_in[8];
    const float* W2    = (const float*)d_in[9];
    const float* b2    = (const float*)d_in[10];
    float* out = (float*)d_out;

    dim3 grid(IMG / TX, IMG / TY, BATCH);
    fused_dclf<<<grid, NT>>>(x, W1, b1, gamma, beta, dw_w, dw_b,
                             pw_w, pw_b, W2, b2, out);
}

// round 4
// speedup vs baseline: 2.5267x; 2.5267x over previous
#include <cuda_runtime.h>
#include <math.h>

#define BATCH 16
#define DIM   48
#define HID   16
#define CH    8
#define IMG   256
#define HW    (IMG*IMG)
#define ROWS  (BATCH*HW)

typedef unsigned long long u64;

__device__ float g_x1[(size_t)ROWS * CH];   // 33.5 MB
__device__ float g_n [(size_t)ROWS * CH];   // 33.5 MB

__device__ __forceinline__ u64 pk2(float a, float b) {
    u64 r;
    asm("mov.b64 %0,{%1,%2};" : "=l"(r) : "r"(__float_as_uint(a)), "r"(__float_as_uint(b)));
    return r;
}
__device__ __forceinline__ void upk2(u64 v, float& a, float& b) {
    unsigned lo, hi;
    asm("mov.b64 {%0,%1},%2;" : "=r"(lo), "=r"(hi) : "l"(v));
    a = __uint_as_float(lo); b = __uint_as_float(hi);
}
__device__ __forceinline__ void fma2(u64& d, u64 a, u64 b) {
    asm("fma.rn.f32x2 %0,%1,%2,%0;" : "+l"(d) : "l"(a), "l"(b));
}
__device__ __forceinline__ u64 mul2(u64 a, u64 b) {
    u64 r;
    asm("mul.rn.f32x2 %0,%1,%2;" : "=l"(r) : "l"(a), "l"(b));
    return r;
}

// Exact-formula GELU via A&S 7.1.26 erf (|abs err| ~1.5e-7, validated R3)
__device__ __forceinline__ float gelu_f(float v) {
    float s = fabsf(v) * 0.7071067811865476f;
    float t = __fdividef(1.0f, fmaf(0.3275911f, s, 1.0f));
    float p = fmaf(1.061405429f, t, -1.453152027f);
    p = fmaf(p, t, 1.421413741f);
    p = fmaf(p, t, -0.284496736f);
    p = fmaf(p, t, 0.254829592f);
    p *= t;
    float e = fmaf(-p, __expf(-s * s), 1.0f);
    e = copysignf(e, v);
    return 0.5f * v * (1.0f + e);
}

// ---------------------------------------------------------------------------
// K1: t = gelu(gelu(x @ W1 + b1)); x1 = t[:,:8]; n = LN(t[:,8:])
// ---------------------------------------------------------------------------
__global__ __launch_bounds__(256) void k1_gemm_gelu_ln(
    const float* __restrict__ x, const float* __restrict__ W1,
    const float* __restrict__ b1, const float* __restrict__ gamma,
    const float* __restrict__ beta)
{
    __shared__ __align__(16) float sW1[DIM * HID];
    __shared__ u64  sb1_2[HID / 2];
    __shared__ float sg[CH], sb[CH];

    int tid = threadIdx.x;
    for (int i = tid; i < DIM * HID; i += 256) sW1[i] = W1[i];
    if (tid < HID / 2) sb1_2[tid] = pk2(b1[2 * tid], b1[2 * tid + 1]);
    if (tid < CH) { sg[tid] = gamma[tid]; sb[tid] = beta[tid]; }
    __syncthreads();

    int r = blockIdx.x * 256 + tid;
    const float4* xr = (const float4*)(x + (size_t)r * DIM);

    u64 z2[8];
    #pragma unroll
    for (int q = 0; q < 8; q++) z2[q] = sb1_2[q];

    #pragma unroll
    for (int k4 = 0; k4 < DIM / 4; k4++) {
        float4 v = xr[k4];
        float xs[4] = {v.x, v.y, v.z, v.w};
        #pragma unroll
        for (int kk = 0; kk < 4; kk++) {
            u64 xx = pk2(xs[kk], xs[kk]);
            const ulonglong2* wr = (const ulonglong2*)&sW1[(k4 * 4 + kk) * HID];
            #pragma unroll
            for (int q2 = 0; q2 < 4; q2++) {
                ulonglong2 w = wr[q2];
                fma2(z2[2 * q2],     xx, w.x);
                fma2(z2[2 * q2 + 1], xx, w.y);
            }
        }
    }

    float z[HID];
    #pragma unroll
    for (int q = 0; q < 8; q++) upk2(z2[q], z[2 * q], z[2 * q + 1]);

    #pragma unroll
    for (int j = 0; j < HID; j++) z[j] = gelu_f(gelu_f(z[j]));

    float4* o1 = (float4*)(g_x1 + (size_t)r * CH);
    o1[0] = make_float4(z[0], z[1], z[2], z[3]);
    o1[1] = make_float4(z[4], z[5], z[6], z[7]);

    float m = 0.f;
    #pragma unroll
    for (int j = 8; j < 16; j++) m += z[j];
    m *= 0.125f;
    float var = 0.f;
    #pragma unroll
    for (int j = 8; j < 16; j++) { float d = z[j] - m; var += d * d; }
    var *= 0.125f;
    float inv = rsqrtf(var + 1e-5f);

    float nn[CH];
    #pragma unroll
    for (int j = 0; j < CH; j++) nn[j] = (z[8 + j] - m) * inv * sg[j] + sb[j];

    float4* o2 = (float4*)(g_n + (size_t)r * CH);
    o2[0] = make_float4(nn[0], nn[1], nn[2], nn[3]);
    o2[1] = make_float4(nn[4], nn[5], nn[6], nn[7]);
}

// ---------------------------------------------------------------------------
// K2: dw3x3 + pw1x1 + gate -> g (smem), then GEMM(8->48) with W2^T,
// 4 px/thread, pixel-pair f32x2 accumulation, STG.128 transposed stores.
// ---------------------------------------------------------------------------
#define TX 32
#define TY 16
#define HAW (TX+2)
#define HAH (TY+2)
#define NH  (HAW*HAH)     // 612
#define NT  256
#define NPIX (TX*TY)      // 512

__global__ __launch_bounds__(NT) void k2_conv_gate_gemm(
    const float* __restrict__ dw_w, const float* __restrict__ dw_b,
    const float* __restrict__ pw_w, const float* __restrict__ pw_b,
    const float* __restrict__ W2,   const float* __restrict__ b2,
    float* __restrict__ out)
{
    __shared__ float4 snA[NH], snB[NH];        // 19.1 KB
    __shared__ float4 sgA[NPIX], sgB[NPIX];    // 16 KB
    __shared__ u64  sdw2[9 * 4], sdwb2[4];
    __shared__ u64  spw2[CH * 4], spwb2[4];
    __shared__ __align__(16) float sW2T[DIM * CH];  // transposed [d][c]
    __shared__ float sb2[DIM];

    const int tid = threadIdx.x;

    if (tid < 36) {                               // dw: [tap][chpair]
        int tap = tid / 4, q = tid % 4;
        sdw2[tid] = pk2(dw_w[(2 * q) * 9 + tap], dw_w[(2 * q + 1) * 9 + tap]);
    }
    if (tid >= 64 && tid < 68)
        sdwb2[tid - 64] = pk2(dw_b[2 * (tid - 64)], dw_b[2 * (tid - 64) + 1]);
    if (tid >= 96 && tid < 128) {                 // pw: [cin][coutpair]
        int c = (tid - 96) / 4, j = (tid - 96) % 4;
        spw2[tid - 96] = pk2(pw_w[(2 * j) * CH + c], pw_w[(2 * j + 1) * CH + c]);
    }
    if (tid >= 128 && tid < 132)
        spwb2[tid - 128] = pk2(pw_b[2 * (tid - 128)], pw_b[2 * (tid - 128) + 1]);
    if (tid >= 160 && tid < 208) sb2[tid - 160] = b2[tid - 160];
    for (int i = tid; i < DIM * CH; i += NT) {    // W2^T
        int d = i / CH, c = i % CH;
        sW2T[i] = W2[c * DIM + d];
    }

    const int b   = blockIdx.z;
    const int tx0 = blockIdx.x * TX;
    const int ty0 = blockIdx.y * TY;
    const float* nb = g_n + (size_t)b * HW * CH;

    // halo load of n
    for (int i = tid; i < NH; i += NT) {
        int hy = i / HAW, hx = i % HAW;
        int gy = ty0 + hy - 1, gx = tx0 + hx - 1;
        float4 a = make_float4(0.f, 0.f, 0.f, 0.f);
        float4 c = make_float4(0.f, 0.f, 0.f, 0.f);
        if (((unsigned)gy < IMG) & ((unsigned)gx < IMG)) {
            const float4* src = (const float4*)(nb + ((size_t)gy * IMG + gx) * CH);
            a = src[0]; c = src[1];
        }
        snA[i] = a; snB[i] = c;
    }
    __syncthreads();

    const ulonglong2* snA2 = (const ulonglong2*)snA;
    const ulonglong2* snB2 = (const ulonglong2*)snB;

    // ---- phase 2a: conv + pw + gate, 2 pixels/thread -> g in smem ----
    #pragma unroll
    for (int rep = 0; rep < NPIX / NT; rep++) {
        int o  = tid + rep * NT;
        int oy = o / TX, ox = o % TX;
        int ci = (oy + 1) * HAW + (ox + 1);

        u64 sp2[4];
        #pragma unroll
        for (int q = 0; q < 4; q++) sp2[q] = sdwb2[q];
        u64 cenA0 = 0, cenA1 = 0, cenB0 = 0, cenB1 = 0;
        #pragma unroll
        for (int dy = 0; dy < 3; dy++) {
            #pragma unroll
            for (int dx = 0; dx < 3; dx++) {
                int idx = ci + (dy - 1) * HAW + (dx - 1);
                ulonglong2 a  = snA2[idx];
                ulonglong2 bv = snB2[idx];
                int tap = dy * 3 + dx;
                fma2(sp2[0], a.x,  sdw2[tap * 4 + 0]);
                fma2(sp2[1], a.y,  sdw2[tap * 4 + 1]);
                fma2(sp2[2], bv.x, sdw2[tap * 4 + 2]);
                fma2(sp2[3], bv.y, sdw2[tap * 4 + 3]);
                if (tap == 4) { cenA0 = a.x; cenA1 = a.y; cenB0 = bv.x; cenB1 = bv.y; }
            }
        }

        float nc[CH];
        upk2(cenA0, nc[0], nc[1]); upk2(cenA1, nc[2], nc[3]);
        upk2(cenB0, nc[4], nc[5]); upk2(cenB1, nc[6], nc[7]);
        u64 ch2[4];
        #pragma unroll
        for (int q = 0; q < 4; q++) ch2[q] = spwb2[q];
        #pragma unroll
        for (int c = 0; c < CH; c++) {
            u64 cc = pk2(nc[c], nc[c]);
            #pragma unroll
            for (int q = 0; q < 4; q++) fma2(ch2[q], cc, spw2[c * 4 + q]);
        }

        int p = (ty0 + oy) * IMG + (tx0 + ox);
        const float4* x1p = (const float4*)(g_x1 + ((size_t)b * HW + p) * CH);
        float4 xa = x1p[0], xv = x1p[1];
        u64 g0 = mul2(mul2(pk2(xa.x, xa.y), sp2[0]), ch2[0]);
        u64 g1 = mul2(mul2(pk2(xa.z, xa.w), sp2[1]), ch2[1]);
        u64 g2v = mul2(mul2(pk2(xv.x, xv.y), sp2[2]), ch2[2]);
        u64 g3 = mul2(mul2(pk2(xv.z, xv.w), sp2[3]), ch2[3]);
        float gf[CH];
        upk2(g0, gf[0], gf[1]); upk2(g1, gf[2], gf[3]);
        upk2(g2v, gf[4], gf[5]); upk2(g3, gf[6], gf[7]);
        sgA[o] = make_float4(gf[0], gf[1], gf[2], gf[3]);
        sgB[o] = make_float4(gf[4], gf[5], gf[6], gf[7]);
    }
    __syncthreads();

    // ---- phase 2b: GEMM 8->48, 4 consecutive px / thread, 24 d's ----
    {
        int half = tid >> 7;          // 0/1 -> d in [0,24) / [24,48)
        int pg   = tid & 127;         // pixel group of 4
        int oy   = pg >> 3, ox4 = (pg & 7) * 4;
        int o0   = oy * TX + ox4;

        float4 a0 = sgA[o0 + 0], b0 = sgB[o0 + 0];
        float4 a1 = sgA[o0 + 1], b1v = sgB[o0 + 1];
        float4 a2 = sgA[o0 + 2], b2v = sgB[o0 + 2];
        float4 a3 = sgA[o0 + 3], b3 = sgB[o0 + 3];

        u64 g01[CH], g23[CH];
        g01[0] = pk2(a0.x, a1.x); g01[1] = pk2(a0.y, a1.y);
        g01[2] = pk2(a0.z, a1.z); g01[3] = pk2(a0.w, a1.w);
        g01[4] = pk2(b0.x, b1v.x); g01[5] = pk2(b0.y, b1v.y);
        g01[6] = pk2(b0.z, b1v.z); g01[7] = pk2(b0.w, b1v.w);
        g23[0] = pk2(a2.x, a3.x); g23[1] = pk2(a2.y, a3.y);
        g23[2] = pk2(a2.z, a3.z); g23[3] = pk2(a2.w, a3.w);
        g23[4] = pk2(b2v.x, b3.x); g23[5] = pk2(b2v.y, b3.y);
        g23[6] = pk2(b2v.z, b3.z); g23[7] = pk2(b2v.w, b3.w);

        int prow = (ty0 + oy) * IMG + tx0 + ox4;
        float* ob = out + (size_t)b * DIM * HW + prow;
        const float4* sW2T4 = (const float4*)sW2T;

        #pragma unroll
        for (int dd = 0; dd < DIM / 2; dd++) {
            int d = half * (DIM / 2) + dd;
            float4 wA = sW2T4[d * 2], wB = sW2T4[d * 2 + 1];
            float bb = sb2[d];
            u64 acc01 = pk2(bb, bb), acc23 = acc01;
            u64 ww;
            ww = pk2(wA.x, wA.x); fma2(acc01, g01[0], ww); fma2(acc23, g23[0], ww);
            ww = pk2(wA.y, wA.y); fma2(acc01, g01[1], ww); fma2(acc23, g23[1], ww);
            ww = pk2(wA.z, wA.z); fma2(acc01, g01[2], ww); fma2(acc23, g23[2], ww);
            ww = pk2(wA.w, wA.w); fma2(acc01, g01[3], ww); fma2(acc23, g23[3], ww);
            ww = pk2(wB.x, wB.x); fma2(acc01, g01[4], ww); fma2(acc23, g23[4], ww);
            ww = pk2(wB.y, wB.y); fma2(acc01, g01[5], ww); fma2(acc23, g23[5], ww);
            ww = pk2(wB.z, wB.z); fma2(acc01, g01[6], ww); fma2(acc23, g23[6], ww);
            ww = pk2(wB.w, wB.w); fma2(acc01, g01[7], ww); fma2(acc23, g23[7], ww);

            float4 o4;
            upk2(acc01, o4.x, o4.y);
            upk2(acc23, o4.z, o4.w);
            *(float4*)(ob + (size_t)d * HW) = o4;
        }
    }
}

extern "C" void kernel_launch(void* const* d_in, const int* in_sizes, int n_in,
                              void* d_out, int out_size)
{
    const float* x     = (const float*)d_in[0];
    const float* W1    = (const float*)d_in[1];
    const float* b1    = (const float*)d_in[2];
    const float* gamma = (const float*)d_in[3];
    const float* beta  = (const float*)d_in[4];
    const float* dw_w  = (const float*)d_in[5];
    const float* dw_b  = (const float*)d_in[6];
    const float* pw_w  = (const float*)d_in[7];
    const float* pw_b  = (const float*)d_in[8];
    const float* W2    = (const float*)d_in[9];
    const float* b2    = (const float*)d_in[10];
    float* out = (float*)d_out;

    k1_gemm_gelu_ln<<<ROWS / 256, 256>>>(x, W1, b1, gamma, beta);

    dim3 g2(IMG / TX, IMG / TY, BATCH);
    k2_conv_gate_gemm<<<g2, NT>>>(dw_w, dw_b, pw_w, pw_b, W2, b2, out);
}